// round 9
// baseline (speedup 1.0000x reference)
#include <cuda_runtime.h>
#include <cuda_bf16.h>
#include <cstdint>

#define T_ 2
#define C_ 64
#define H_ 160
#define W_ 160
#define KS 7
#define K2 49
#define NSPIX 196
#define FAN 3136

#define TH 8
#define TW 8
#define NPIX 64
#define XR 14
#define XC 14
#define NS 196         // XR*XC
#define HROW 144       // 64B digit1 + 64B digit2 + 16 pad

// ---- dynamic smem layout (bytes) ----
#define OFF_HALO   0                   // 196*144 = 28224
#define OFF_B      28224               // 2 bufs * 8192 = 16384
#define OFF_RW     44608               // 64*49*4 = 12544
#define OFF_SCALE  57152               // 64*4 = 256
#define SMEM_MAIN  57408

#define PWD_STRIDE 67
#define PWD_SMEM   (NSPIX*PWD_STRIDE*4 + NSPIX*4)   // 53312

// ---- global scratch ----
__device__ float g_sums[T_*NSPIX*C_];
__device__ float g_cnts[T_*NSPIX];
__device__ float g_pwd[T_*NSPIX*NSPIX];
__device__ unsigned g_max[2];          // abs-bits max of x, W
__device__ float g_S[8];               // inv1x, s1x, inv2x, inv1w, s1w, inv2w, Sc
// per k: 64 o-rows of 128B = [digit1 64B | digit2 64B], XOR-swizzled 16B chunks
__device__ __align__(16) signed char g_Wq[K2*C_*128];

__device__ __forceinline__ int refl(int i, int n){
    if (i < 0) i = -i;
    if (i >= n) i = 2*n - 2 - i;
    return i;
}

__device__ __forceinline__ uint32_t smem_u32(const void* p){
    uint32_t a;
    asm("{ .reg .u64 t; cvta.to.shared.u64 t, %1; cvt.u32.u64 %0, t; }" : "=r"(a) : "l"(p));
    return a;
}

__device__ __forceinline__ void ldsm4(uint32_t* r, uint32_t addr){
    asm volatile("ldmatrix.sync.aligned.m8n8.x4.shared.b16 {%0,%1,%2,%3}, [%4];"
        : "=r"(r[0]), "=r"(r[1]), "=r"(r[2]), "=r"(r[3]) : "r"(addr));
}

__device__ __forceinline__ void imma(int* d, const uint32_t* a, const uint32_t* b){
    asm volatile("mma.sync.aligned.m16n8k32.row.col.s32.s8.s8.s32 "
        "{%0,%1,%2,%3}, {%4,%5,%6,%7}, {%8,%9}, {%0,%1,%2,%3};"
        : "+r"(d[0]), "+r"(d[1]), "+r"(d[2]), "+r"(d[3])
        : "r"(a[0]), "r"(a[1]), "r"(a[2]), "r"(a[3]), "r"(b[0]), "r"(b[1]));
}

__device__ __forceinline__ void cpa16(uint32_t dst, const void* src){
    asm volatile("cp.async.cg.shared.global [%0], [%1], 16;" :: "r"(dst), "l"(src) : "memory");
}
#define CP_COMMIT() asm volatile("cp.async.commit_group;" ::: "memory")
#define CP_WAIT(n)  asm volatile("cp.async.wait_group %0;" :: "n"(n) : "memory")

__device__ __forceinline__ int q8(float v, float inv){ return __float2int_rn(v*inv); }

// ========================= prep kernels =========================

__global__ void zero_kernel(){
    int i = blockIdx.x*blockDim.x + threadIdx.x;
    if (i < T_*NSPIX*C_) g_sums[i] = 0.f;
    if (i < T_*NSPIX)    g_cnts[i] = 0.f;
    if (i < 2)           g_max[i] = 0u;
}

__global__ void maxabs_kernel(const float* __restrict__ p, int n, int slot){
    __shared__ unsigned red[8];
    int tid = threadIdx.x;
    unsigned m = 0;
    for (int i = blockIdx.x*256 + tid; i < n; i += gridDim.x*256)
        m = max(m, __float_as_uint(fabsf(p[i])));
    #pragma unroll
    for (int o = 16; o; o >>= 1) m = max(m, __shfl_xor_sync(0xffffffffu, m, o));
    if ((tid & 31) == 0) red[tid >> 5] = m;
    __syncthreads();
    if (tid < 8){
        m = red[tid];
        #pragma unroll
        for (int o = 4; o; o >>= 1) m = max(m, __shfl_xor_sync(0xffu, m, o));
        if (tid == 0) atomicMax(&g_max[slot], m);
    }
}

__global__ void scale_kernel(){
    float mx = fmaxf(__uint_as_float(g_max[0]), 1e-20f);
    float mw = fmaxf(__uint_as_float(g_max[1]), 1e-20f);
    float s1x = mx / 127.f, s1w = mw / 127.f;
    g_S[0] = 127.f/mx;  g_S[1] = s1x;  g_S[2] = 254.f/s1x;
    g_S[3] = 127.f/mw;  g_S[4] = s1w;  g_S[5] = 254.f/s1w;
    g_S[6] = s1x*s1w/254.f;
}

// grid 64 (one block per o): quantize W to 2 int8 digits, swizzled rows.
__global__ void wsplit_kernel(const float* __restrict__ W){
    __shared__ float wrow[FAN];
    int o = blockIdx.x;
    int tid = threadIdx.x;
    for (int i = tid; i < FAN; i += 256) wrow[i] = W[o*FAN + i];
    __syncthreads();
    float inv1 = g_S[3], s1 = g_S[4], inv2 = g_S[5];
    uint32_t oxor = (uint32_t)((o & 7) << 4);
    signed char* base = (signed char*)g_Wq;
    for (int idx = tid; idx < FAN; idx += 256){
        int k = idx >> 6, c = idx & 63;
        float v = wrow[c*K2 + k];
        int a1 = q8(v, inv1);
        float r = v - (float)a1*s1;
        int a2 = q8(r, inv2);
        uint32_t inner = (uint32_t)(c & 15);
        uint32_t ch1 = (uint32_t)(c >> 4);          // 0..3
        uint32_t row = (uint32_t)(k*C_ + o)*128u;
        base[row + ((ch1<<4) ^ oxor) + inner]       = (signed char)a1;
        base[row + (((ch1+4)<<4) ^ oxor) + inner]   = (signed char)a2;
    }
}

// one warp per pixel: lanes = channels -> coalesced RED
__global__ void accum_kernel(const float* __restrict__ x, const int* __restrict__ spix){
    int tid = threadIdx.x;
    int wi = tid >> 5, l = tid & 31;
    int pix = blockIdx.x*8 + wi;
    if (pix >= T_*H_*W_) return;
    int t = pix / (H_*W_);
    int hw = pix - t*(H_*W_);
    int s = spix[pix];
    const float* xp = x + (size_t)t*C_*H_*W_ + hw;
    float v0 = xp[(size_t)l*(H_*W_)];
    float v1 = xp[(size_t)(l+32)*(H_*W_)];
    float* dst = &g_sums[(t*NSPIX + s)*C_];
    atomicAdd(&dst[l],      v0);
    atomicAdd(&dst[l + 32], v1);
    if (l == 0) atomicAdd(&g_cnts[t*NSPIX + s], 1.0f);
}

// grid T_*49, 256 threads. Coalesced load, stride-67 pad, thread = s, 4 u per block.
__global__ void pwd_kernel(){
    extern __shared__ float sm[];
    float* down = sm;                       // [196][67]
    float* sq   = sm + NSPIX*PWD_STRIDE;
    int t  = blockIdx.x / 49;
    int ub = (blockIdx.x % 49) * 4;
    int tid = threadIdx.x;
    for (int i = tid; i < NSPIX*C_; i += 256){
        int s = i >> 6, c = i & 63;
        float cinv = 1.f / fmaxf(g_cnts[t*NSPIX + s], 1.f);
        down[s*PWD_STRIDE + c] = g_sums[i + t*NSPIX*C_] * cinv;
    }
    __syncthreads();
    if (tid < NSPIX){
        float q = 0.f;
        const float* a = &down[tid*PWD_STRIDE];
        #pragma unroll 8
        for (int c = 0; c < C_; c++) q += a[c]*a[c];
        sq[tid] = q;
    }
    __syncthreads();
    if (tid < NSPIX){
        const float* a = &down[tid*PWD_STRIDE];
        const float* u0 = &down[(ub+0)*PWD_STRIDE];
        const float* u1 = &down[(ub+1)*PWD_STRIDE];
        const float* u2 = &down[(ub+2)*PWD_STRIDE];
        const float* u3 = &down[(ub+3)*PWD_STRIDE];
        float d0=0.f, d1=0.f, d2=0.f, d3=0.f;
        #pragma unroll 8
        for (int c = 0; c < C_; c++){
            float av = a[c];
            d0 += av*u0[c]; d1 += av*u1[c]; d2 += av*u2[c]; d3 += av*u3[c];
        }
        float qs = sq[tid];
        float* dst = &g_pwd[(size_t)(t*NSPIX + tid)*NSPIX + ub];
        dst[0] = fmaxf(qs + sq[ub+0] - 2.f*d0, 0.f);
        dst[1] = fmaxf(qs + sq[ub+1] - 2.f*d1, 0.f);
        dst[2] = fmaxf(qs + sq[ub+2] - 2.f*d2, 0.f);
        dst[3] = fmaxf(qs + sq[ub+3] - 2.f*d3, 0.f);
    }
}

// ========================= main kernel =========================
// 800 CTAs (8x8 px), 256 threads (8 warps: 4m x 2n), occ 2.

__global__ void __launch_bounds__(256, 2) main_kernel(
    const float* __restrict__ x, const int* __restrict__ spix,
    const float* __restrict__ b_lin, const float* __restrict__ w_scale,
    const float* __restrict__ b_scale, float* __restrict__ out)
{
    extern __shared__ char smem[];
    uint32_t sb = smem_u32(smem);
    int tid = threadIdx.x;
    int wi = tid >> 5, l = tid & 31;
    int mi = wi >> 1, ni = wi & 1;
    int t = blockIdx.z;
    int gh0 = blockIdx.y*TH, gw0 = blockIdx.x*TW;

    float* scale_s = (float*)(smem + OFF_SCALE);
    float* rw      = (float*)(smem + OFF_RW);

    float inv1x = g_S[0], s1x = g_S[1], inv2x = g_S[2], Sc = g_S[6];

    // ---- phase 1: per-pixel scale ----
    if (tid < NPIX){
        int gh = gh0 + (tid >> 3), gw = gw0 + (tid & 7);
        const float* xp = x + (size_t)t*C_*H_*W_ + gh*W_ + gw;
        float nsq = 0.f, dot = 0.f;
        #pragma unroll 8
        for (int c = 0; c < C_; c++){
            float v = xp[(size_t)c*H_*W_];
            nsq += v*v;
            dot += w_scale[c]*v;
        }
        float z  = dot / (sqrtf(nsq) + 1e-10f) + b_scale[0];
        float sp = fmaxf(z, 0.f) + log1pf(expf(-fabsf(z)));
        scale_s[tid] = 10.f * sp;
    }

    // ---- phase 2: halo load + 2-digit int8 quantize: row s = [d1 64B][d2 64B][pad] ----
    for (int i = tid; i < NS*16; i += 256){
        int q  = i / NS;          // channel quad 0..15
        int s  = i - q*NS;
        int rr = s / XC, cc2 = s - rr*XC;
        int gh = refl(gh0 + rr - 3, H_), gw = refl(gw0 + cc2 - 3, W_);
        const float* xp = x + ((size_t)(t*C_ + 4*q)*H_ + gh)*W_ + gw;
        uint32_t u1 = 0, u2 = 0;
        #pragma unroll
        for (int j = 0; j < 4; j++){
            float v = xp[(size_t)j*H_*W_];
            int a1 = q8(v, inv1x);
            float r = v - (float)a1*s1x;
            int a2 = q8(r, inv2x);
            u1 |= ((uint32_t)a1 & 0xFFu) << (j*8);
            u2 |= ((uint32_t)a2 & 0xFFu) << (j*8);
        }
        *(uint32_t*)(smem + OFF_HALO + s*HROW + q*4)      = u1;
        *(uint32_t*)(smem + OFF_HALO + s*HROW + 64 + q*4) = u2;
    }
    __syncthreads();

    // ---- phase 3: rw ----
    for (int item = tid; item < NPIX*K2; item += 256){
        int p  = item / K2, k = item - p*K2;
        int ki = k / KS,  kj = k - ki*KS;
        int gh = gh0 + (p >> 3), gw = gw0 + (p & 7);
        int rh = refl(gh + ki - 3, H_), rc = refl(gw + kj - 3, W_);
        int sc = spix[(t*H_ + gh)*W_ + gw];
        int nb = spix[(t*H_ + rh)*W_ + rc];
        rw[item] = expf(-scale_s[p] * g_pwd[(size_t)(t*NSPIX + sc)*NSPIX + nb]);
    }
    __syncthreads();
    if (tid < NPIX){
        float m = 0.f;
        #pragma unroll
        for (int k = 0; k < K2; k++) m = fmaxf(m, rw[tid*K2 + k]);
        float inv = 1.f / (1e-5f + m);
        #pragma unroll
        for (int k = 0; k < K2; k++) rw[tid*K2 + k] *= inv;
    }

    // ---- per-lane static addressing ----
    int rowA = (l & 7) | (((l >> 3) & 1) << 3);
    int colh = (l >> 4) & 1;
    int pA   = mi*16 + rowA;
    uint32_t aStat = sb + OFF_HALO + (uint32_t)(((pA >> 3)*XC + (pA & 7))*HROW) + colh*16;

    int oRow  = (l & 7) | (((l >> 4) & 1) << 3);
    uint32_t bhalf16 = (uint32_t)(((l >> 3) & 1) << 4);
    int o0 = ni*32 + oRow;
    int o1 = o0 + 16;
    uint32_t bOff0 = (uint32_t)(o0*128), bXor0 = (uint32_t)((o0 & 7) << 4);
    uint32_t bOff1 = (uint32_t)(o1*128), bXor1 = (uint32_t)((o1 & 7) << 4);

    // ---- preload B for k=0 (8KB: 512 x 16B, 2 per thread) ----
    {
        const char* src = (const char*)g_Wq;
        uint32_t dst = sb + OFF_B;
        cpa16(dst + tid*16,        src + tid*16);
        cpa16(dst + (tid+256)*16,  src + (tid+256)*16);
        CP_COMMIT();
    }

    float acc[16];
    #pragma unroll
    for (int i = 0; i < 16; i++) acc[i] = 0.f;

    int p_lo = mi*16 + (l >> 2);

    // ---- main loop over 49 kernel offsets ----
    for (int k = 0; k < K2; k++){
        int cur = k & 1;
        if (k + 1 < K2){
            const char* src = (const char*)g_Wq + (size_t)(k+1)*8192;
            uint32_t dst = sb + OFF_B + (cur^1)*8192;
            cpa16(dst + tid*16,       src + tid*16);
            cpa16(dst + (tid+256)*16, src + (tid+256)*16);
            CP_COMMIT();
            CP_WAIT(1);
        } else {
            CP_WAIT(0);
        }
        __syncthreads();

        uint32_t bBase = sb + OFF_B + cur*8192;
        int ki = k / KS, kj = k - ki*KS;
        uint32_t aAddr0 = aStat + (uint32_t)((ki*XC + kj)*HROW);

        int dA[16], dB[16];
        #pragma unroll
        for (int i = 0; i < 16; i++){ dA[i] = 0; dB[i] = 0; }

        #pragma unroll
        for (int kc = 0; kc < 2; kc++){
            uint32_t a1f[4], a2f[4];
            ldsm4(a1f, aAddr0 + kc*32);
            ldsm4(a2f, aAddr0 + 64 + kc*32);

            uint32_t csw = (uint32_t)(kc*32) + bhalf16;       // digit1 chunk sel
            uint32_t b1g0[4], b1g1[4], b2g0[4], b2g1[4];
            ldsm4(b1g0, bBase + bOff0 + (csw ^ bXor0));
            ldsm4(b1g1, bBase + bOff1 + (csw ^ bXor1));
            ldsm4(b2g0, bBase + bOff0 + ((csw + 64) ^ bXor0));
            ldsm4(b2g1, bBase + bOff1 + ((csw + 64) ^ bXor1));

            // pass a1*b1 -> dA
            imma(&dA[0],  a1f, b1g0);
            imma(&dA[4],  a1f, b1g0+2);
            imma(&dA[8],  a1f, b1g1);
            imma(&dA[12], a1f, b1g1+2);
            // pass a1*b2 -> dB
            imma(&dB[0],  a1f, b2g0);
            imma(&dB[4],  a1f, b2g0+2);
            imma(&dB[8],  a1f, b2g1);
            imma(&dB[12], a1f, b2g1+2);
            // pass a2*b1 -> dB (same scale as a1*b2)
            imma(&dB[0],  a2f, b1g0);
            imma(&dB[4],  a2f, b1g0+2);
            imma(&dB[8],  a2f, b1g1);
            imma(&dB[12], a2f, b1g1+2);
        }

        // combine digits + weight by rw
        float rs_lo = rw[p_lo*K2 + k]*Sc;
        float rs_hi = rw[(p_lo + 8)*K2 + k]*Sc;
        #pragma unroll
        for (int g = 0; g < 4; g++){
            acc[g*4+0] += rs_lo*(float)(dA[g*4+0]*254 + dB[g*4+0]);
            acc[g*4+1] += rs_lo*(float)(dA[g*4+1]*254 + dB[g*4+1]);
            acc[g*4+2] += rs_hi*(float)(dA[g*4+2]*254 + dB[g*4+2]);
            acc[g*4+3] += rs_hi*(float)(dA[g*4+3]*254 + dB[g*4+3]);
        }
        __syncthreads();   // all warps done with B buf before overwrite
    }

    // ---- store ----
    {
        int p_hi  = p_lo + 8;
        int gh_lo = gh0 + (p_lo >> 3), gw_lo = gw0 + (p_lo & 7);
        int gh_hi = gh0 + (p_hi >> 3), gw_hi = gw0 + (p_hi & 7);
        #pragma unroll
        for (int g = 0; g < 4; g++){
            int o = ni*32 + g*8 + 2*(l & 3);
            float b0 = b_lin[o], b1 = b_lin[o+1];
            out[((size_t)(t*C_ + o  )*H_ + gh_lo)*W_ + gw_lo] = acc[g*4 + 0] + b0;
            out[((size_t)(t*C_ + o+1)*H_ + gh_lo)*W_ + gw_lo] = acc[g*4 + 1] + b1;
            out[((size_t)(t*C_ + o  )*H_ + gh_hi)*W_ + gw_hi] = acc[g*4 + 2] + b0;
            out[((size_t)(t*C_ + o+1)*H_ + gh_hi)*W_ + gw_hi] = acc[g*4 + 3] + b1;
        }
    }
}

// ========================= launch =========================

extern "C" void kernel_launch(void* const* d_in, const int* in_sizes, int n_in,
                              void* d_out, int out_size)
{
    const float* x       = (const float*)d_in[0];
    const int*   spix    = (const int*)  d_in[1];
    const float* W       = (const float*)d_in[2];
    const float* b_lin   = (const float*)d_in[3];
    const float* w_scale = (const float*)d_in[4];
    const float* b_scale = (const float*)d_in[5];
    float* out = (float*)d_out;

    cudaFuncSetAttribute(pwd_kernel,  cudaFuncAttributeMaxDynamicSharedMemorySize, PWD_SMEM);
    cudaFuncSetAttribute(main_kernel, cudaFuncAttributeMaxDynamicSharedMemorySize, SMEM_MAIN);

    zero_kernel  <<<(T_*NSPIX*C_ + 255)/256, 256>>>();
    maxabs_kernel<<<256, 256>>>(x, T_*C_*H_*W_, 0);
    maxabs_kernel<<<64, 256>>>(W, C_*FAN, 1);
    scale_kernel <<<1, 1>>>();
    wsplit_kernel<<<C_, 256>>>(W);
    accum_kernel <<<(T_*H_*W_ + 7)/8, 256>>>(x, spix);
    pwd_kernel   <<<T_*49, 256, PWD_SMEM>>>();

    dim3 grid(W_/TW, H_/TH, T_);
    main_kernel<<<grid, 256, SMEM_MAIN>>>(x, spix, b_lin, w_scale, b_scale, out);
}

// round 12
// speedup vs baseline: 2.4900x; 2.4900x over previous
#include <cuda_runtime.h>
#include <cuda_fp16.h>
#include <cstdint>

#define T_ 2
#define C_ 64
#define H_ 160
#define W_ 160
#define KS 7
#define K2 49
#define NSPIX 196
#define FAN 3136

#define TH 8
#define TW 8
#define NPIX 64
#define XR 14
#define XC 14
#define NS 196         // XR*XC
#define HROW 272       // 128B x_hi (64 fp16) + 128B x_lo + 16 pad

// ---- dynamic smem layout (bytes) ----
#define OFF_HALO   0                   // 196*272 = 53312
#define OFF_B      53312               // 2 bufs * 8192 = 16384
#define OFF_RW     69696               // 64*49*4 = 12544
#define OFF_SCALE  82240               // 64*4 = 256
#define SMEM_MAIN  82496

#define PWD_STRIDE 67
#define PWD_SMEM   (NSPIX*PWD_STRIDE*4 + NSPIX*4)   // 53312

// ---- global scratch ----
__device__ float g_sums[T_*NSPIX*C_];
__device__ float g_cnts[T_*NSPIX];
__device__ float g_pwd[T_*NSPIX*NSPIX];
// per k: 8192B = 64 o-rows of 128B (64 fp16 c-values), XOR-swizzled 16B chunks
__device__ __align__(16) __half g_Wh[K2*C_*C_];

__device__ __forceinline__ int refl(int i, int n){
    if (i < 0) i = -i;
    if (i >= n) i = 2*n - 2 - i;
    return i;
}

__device__ __forceinline__ uint32_t smem_u32(const void* p){
    uint32_t a;
    asm("{ .reg .u64 t; cvta.to.shared.u64 t, %1; cvt.u32.u64 %0, t; }" : "=r"(a) : "l"(p));
    return a;
}

__device__ __forceinline__ void ldsm4(uint32_t* r, uint32_t addr){
    asm volatile("ldmatrix.sync.aligned.m8n8.x4.shared.b16 {%0,%1,%2,%3}, [%4];"
        : "=r"(r[0]), "=r"(r[1]), "=r"(r[2]), "=r"(r[3]) : "r"(addr));
}

__device__ __forceinline__ void mma16816(float* d, const uint32_t* a, const uint32_t* b){
    asm volatile("mma.sync.aligned.m16n8k16.row.col.f32.f16.f16.f32 "
        "{%0,%1,%2,%3}, {%4,%5,%6,%7}, {%8,%9}, {%0,%1,%2,%3};"
        : "+f"(d[0]), "+f"(d[1]), "+f"(d[2]), "+f"(d[3])
        : "r"(a[0]), "r"(a[1]), "r"(a[2]), "r"(a[3]), "r"(b[0]), "r"(b[1]));
}

__device__ __forceinline__ void cpa16(uint32_t dst, const void* src){
    asm volatile("cp.async.cg.shared.global [%0], [%1], 16;" :: "r"(dst), "l"(src) : "memory");
}
#define CP_COMMIT() asm volatile("cp.async.commit_group;" ::: "memory")
#define CP_WAIT(n)  asm volatile("cp.async.wait_group %0;" :: "n"(n) : "memory")

// ========================= prep kernels =========================

// blocks 0..63: convert W row o=blockIdx to swizzled fp16; blocks 64..163: zero scratch
__global__ void prep_kernel(const float* __restrict__ W){
    int b = blockIdx.x;
    int tid = threadIdx.x;
    if (b < C_){
        __shared__ float wrow[FAN];
        int o = b;
        for (int i = tid; i < FAN; i += 256) wrow[i] = W[o*FAN + i];
        __syncthreads();
        uint32_t oxor = (uint32_t)((o & 7) << 4);
        char* base = (char*)g_Wh;
        for (int idx = tid; idx < FAN; idx += 256){
            int k = idx >> 6, c = idx & 63;
            __half hv = __float2half_rn(wrow[c*K2 + k]);
            uint32_t boff = (uint32_t)(k*8192 + o*128)
                          + ((((uint32_t)(c>>3))<<4) ^ oxor) + (uint32_t)((c&7)*2);
            *(unsigned short*)(base + boff) = __half_as_ushort(hv);
        }
    } else {
        int i = (b - C_)*256 + tid;
        if (i < T_*NSPIX*C_) g_sums[i] = 0.f;
        if (i < T_*NSPIX)    g_cnts[i] = 0.f;
    }
}

// one warp per pixel: lanes = channels -> coalesced RED
__global__ void accum_kernel(const float* __restrict__ x, const int* __restrict__ spix){
    int tid = threadIdx.x;
    int wi = tid >> 5, l = tid & 31;
    int pix = blockIdx.x*8 + wi;
    if (pix >= T_*H_*W_) return;
    int t = pix / (H_*W_);
    int hw = pix - t*(H_*W_);
    int s = spix[pix];
    const float* xp = x + (size_t)t*C_*H_*W_ + hw;
    float v0 = xp[(size_t)l*(H_*W_)];
    float v1 = xp[(size_t)(l+32)*(H_*W_)];
    float* dst = &g_sums[(t*NSPIX + s)*C_];
    atomicAdd(&dst[l],      v0);
    atomicAdd(&dst[l + 32], v1);
    if (l == 0) atomicAdd(&g_cnts[t*NSPIX + s], 1.0f);
}

// grid T_*49, 256 threads. Coalesced load, stride-67 pad, thread = s, 4 u per block.
__global__ void pwd_kernel(){
    extern __shared__ float sm[];
    float* down = sm;                       // [196][67]
    float* sq   = sm + NSPIX*PWD_STRIDE;
    int t  = blockIdx.x / 49;
    int ub = (blockIdx.x % 49) * 4;
    int tid = threadIdx.x;
    for (int i = tid; i < NSPIX*C_; i += 256){
        int s = i >> 6, c = i & 63;
        float cinv = 1.f / fmaxf(g_cnts[t*NSPIX + s], 1.f);
        down[s*PWD_STRIDE + c] = g_sums[i + t*NSPIX*C_] * cinv;
    }
    __syncthreads();
    if (tid < NSPIX){
        float q = 0.f;
        const float* a = &down[tid*PWD_STRIDE];
        #pragma unroll 8
        for (int c = 0; c < C_; c++) q += a[c]*a[c];
        sq[tid] = q;
    }
    __syncthreads();
    if (tid < NSPIX){
        const float* a = &down[tid*PWD_STRIDE];
        const float* u0 = &down[(ub+0)*PWD_STRIDE];
        const float* u1 = &down[(ub+1)*PWD_STRIDE];
        const float* u2 = &down[(ub+2)*PWD_STRIDE];
        const float* u3 = &down[(ub+3)*PWD_STRIDE];
        float d0=0.f, d1=0.f, d2=0.f, d3=0.f;
        #pragma unroll 8
        for (int c = 0; c < C_; c++){
            float av = a[c];
            d0 += av*u0[c]; d1 += av*u1[c]; d2 += av*u2[c]; d3 += av*u3[c];
        }
        float qs = sq[tid];
        float* dst = &g_pwd[(size_t)(t*NSPIX + tid)*NSPIX + ub];
        dst[0] = fmaxf(qs + sq[ub+0] - 2.f*d0, 0.f);
        dst[1] = fmaxf(qs + sq[ub+1] - 2.f*d1, 0.f);
        dst[2] = fmaxf(qs + sq[ub+2] - 2.f*d2, 0.f);
        dst[3] = fmaxf(qs + sq[ub+3] - 2.f*d3, 0.f);
    }
}

// ========================= main kernel =========================
// 800 CTAs (8x8 px), 256 threads (8 warps: 4m x 2n), occ 2.
// fp16 2-pass: out = (x_hi + x_lo) * fp16(W), fp32 accumulate.

__global__ void __launch_bounds__(256, 2) main_kernel(
    const float* __restrict__ x, const int* __restrict__ spix,
    const float* __restrict__ b_lin, const float* __restrict__ w_scale,
    const float* __restrict__ b_scale, float* __restrict__ out)
{
    extern __shared__ char smem[];
    uint32_t sb = smem_u32(smem);
    int tid = threadIdx.x;
    int wi = tid >> 5, l = tid & 31;
    int mi = wi >> 1, ni = wi & 1;
    int t = blockIdx.z;
    int gh0 = blockIdx.y*TH, gw0 = blockIdx.x*TW;

    float* scale_s = (float*)(smem + OFF_SCALE);
    float* rw      = (float*)(smem + OFF_RW);

    // ---- phase 1: per-pixel scale ----
    if (tid < NPIX){
        int gh = gh0 + (tid >> 3), gw = gw0 + (tid & 7);
        const float* xp = x + (size_t)t*C_*H_*W_ + gh*W_ + gw;
        float nsq = 0.f, dot = 0.f;
        #pragma unroll 8
        for (int c = 0; c < C_; c++){
            float v = xp[(size_t)c*H_*W_];
            nsq += v*v;
            dot += w_scale[c]*v;
        }
        float z  = dot / (sqrtf(nsq) + 1e-10f) + b_scale[0];
        float sp = fmaxf(z, 0.f) + log1pf(expf(-fabsf(z)));
        scale_s[tid] = 10.f * sp;
    }

    // ---- phase 2: halo load + fp16 hi/lo split: row s = [hi 128B][lo 128B][pad] ----
    for (int i = tid; i < NS*32; i += 256){
        int s  = i >> 5;
        int cp = i & 31;          // channel pair
        int rr = s / XC, cc2 = s - rr*XC;
        int gh = refl(gh0 + rr - 3, H_), gw = refl(gw0 + cc2 - 3, W_);
        const float* xp = x + ((size_t)(t*C_ + 2*cp)*H_ + gh)*W_ + gw;
        float v0 = xp[0], v1 = xp[(size_t)H_*W_];
        __half h0 = __float2half_rn(v0), h1 = __float2half_rn(v1);
        float l0 = v0 - __half2float(h0);
        float l1 = v1 - __half2float(h1);
        __half g0 = __float2half_rn(l0), g1 = __float2half_rn(l1);
        uint32_t uh = (uint32_t)__half_as_ushort(h0) | ((uint32_t)__half_as_ushort(h1) << 16);
        uint32_t ul = (uint32_t)__half_as_ushort(g0) | ((uint32_t)__half_as_ushort(g1) << 16);
        *(uint32_t*)(smem + OFF_HALO + s*HROW + cp*4)       = uh;
        *(uint32_t*)(smem + OFF_HALO + s*HROW + 128 + cp*4) = ul;
    }
    __syncthreads();

    // ---- phase 3: rw ----
    for (int item = tid; item < NPIX*K2; item += 256){
        int p  = item / K2, k = item - p*K2;
        int ki = k / KS,  kj = k - ki*KS;
        int gh = gh0 + (p >> 3), gw = gw0 + (p & 7);
        int rh = refl(gh + ki - 3, H_), rc = refl(gw + kj - 3, W_);
        int sc = spix[(t*H_ + gh)*W_ + gw];
        int nb = spix[(t*H_ + rh)*W_ + rc];
        rw[item] = expf(-scale_s[p] * g_pwd[(size_t)(t*NSPIX + sc)*NSPIX + nb]);
    }
    __syncthreads();
    if (tid < NPIX){
        float m = 0.f;
        #pragma unroll
        for (int k = 0; k < K2; k++) m = fmaxf(m, rw[tid*K2 + k]);
        float inv = 1.f / (1e-5f + m);
        #pragma unroll
        for (int k = 0; k < K2; k++) rw[tid*K2 + k] *= inv;
    }

    // ---- per-lane static addressing ----
    int rowA = (l & 7) | (((l >> 3) & 1) << 3);
    int colh = (l >> 4) & 1;
    int pA   = mi*16 + rowA;
    uint32_t aStat = sb + OFF_HALO + (uint32_t)(((pA >> 3)*XC + (pA & 7))*HROW) + colh*16;

    int oRow  = (l & 7) | (((l >> 4) & 1) << 3);
    uint32_t bhalf16 = (uint32_t)(((l >> 3) & 1) << 4);
    int o0 = ni*32 + oRow;
    int o1 = o0 + 16;
    uint32_t bOff0 = (uint32_t)(o0*128), bXor0 = (uint32_t)((o0 & 7) << 4);
    uint32_t bOff1 = (uint32_t)(o1*128), bXor1 = (uint32_t)((o1 & 7) << 4);

    // ---- preload B for k=0 (8KB: 512 x 16B, 2 per thread) ----
    {
        const char* src = (const char*)g_Wh;
        uint32_t dst = sb + OFF_B;
        cpa16(dst + tid*16,       src + tid*16);
        cpa16(dst + (tid+256)*16, src + (tid+256)*16);
        CP_COMMIT();
    }

    float acc[16];
    #pragma unroll
    for (int i = 0; i < 16; i++) acc[i] = 0.f;

    int p_lo = mi*16 + (l >> 2);

    // ---- main loop over 49 kernel offsets ----
    for (int k = 0; k < K2; k++){
        int cur = k & 1;
        if (k + 1 < K2){
            const char* src = (const char*)g_Wh + (size_t)(k+1)*8192;
            uint32_t dst = sb + OFF_B + (cur^1)*8192;
            cpa16(dst + tid*16,       src + tid*16);
            cpa16(dst + (tid+256)*16, src + (tid+256)*16);
            CP_COMMIT();
            CP_WAIT(1);
        } else {
            CP_WAIT(0);
        }
        __syncthreads();

        uint32_t bBase = sb + OFF_B + cur*8192;
        int ki = k / KS, kj = k - ki*KS;
        uint32_t aAddr0 = aStat + (uint32_t)((ki*XC + kj)*HROW);

        float d[16];
        #pragma unroll
        for (int i = 0; i < 16; i++) d[i] = 0.f;

        #pragma unroll
        for (int kc = 0; kc < 4; kc++){
            uint32_t aH[4], aL[4];
            uint32_t aAddr = aAddr0 + kc*32;
            ldsm4(aH, aAddr);
            ldsm4(aL, aAddr + 128);

            uint32_t csw = (uint32_t)(kc*32) + bhalf16;
            uint32_t b0[4], b1[4];
            ldsm4(b0, bBase + bOff0 + (csw ^ bXor0));
            ldsm4(b1, bBase + bOff1 + (csw ^ bXor1));

            // pass x_hi * W
            mma16816(&d[0],  aH, b0);
            mma16816(&d[4],  aH, b0+2);
            mma16816(&d[8],  aH, b1);
            mma16816(&d[12], aH, b1+2);
            // pass x_lo * W
            mma16816(&d[0],  aL, b0);
            mma16816(&d[4],  aL, b0+2);
            mma16816(&d[8],  aL, b1);
            mma16816(&d[12], aL, b1+2);
        }

        // weight by rw and accumulate
        float r_lo = rw[p_lo*K2 + k];
        float r_hi = rw[(p_lo + 8)*K2 + k];
        #pragma unroll
        for (int g = 0; g < 4; g++){
            acc[g*4 + 0] += r_lo*d[g*4 + 0];
            acc[g*4 + 1] += r_lo*d[g*4 + 1];
            acc[g*4 + 2] += r_hi*d[g*4 + 2];
            acc[g*4 + 3] += r_hi*d[g*4 + 3];
        }
        __syncthreads();   // all warps done with B buf before overwrite
    }

    // ---- store ----
    {
        int p_hi  = p_lo + 8;
        int gh_lo = gh0 + (p_lo >> 3), gw_lo = gw0 + (p_lo & 7);
        int gh_hi = gh0 + (p_hi >> 3), gw_hi = gw0 + (p_hi & 7);
        #pragma unroll
        for (int g = 0; g < 4; g++){
            int o = ni*32 + g*8 + 2*(l & 3);
            float b0 = b_lin[o], b1 = b_lin[o+1];
            out[((size_t)(t*C_ + o  )*H_ + gh_lo)*W_ + gw_lo] = acc[g*4 + 0] + b0;
            out[((size_t)(t*C_ + o+1)*H_ + gh_lo)*W_ + gw_lo] = acc[g*4 + 1] + b1;
            out[((size_t)(t*C_ + o  )*H_ + gh_hi)*W_ + gw_hi] = acc[g*4 + 2] + b0;
            out[((size_t)(t*C_ + o+1)*H_ + gh_hi)*W_ + gw_hi] = acc[g*4 + 3] + b1;
        }
    }
}

// ========================= launch =========================

extern "C" void kernel_launch(void* const* d_in, const int* in_sizes, int n_in,
                              void* d_out, int out_size)
{
    const float* x       = (const float*)d_in[0];
    const int*   spix    = (const int*)  d_in[1];
    const float* W       = (const float*)d_in[2];
    const float* b_lin   = (const float*)d_in[3];
    const float* w_scale = (const float*)d_in[4];
    const float* b_scale = (const float*)d_in[5];
    float* out = (float*)d_out;

    cudaFuncSetAttribute(pwd_kernel,  cudaFuncAttributeMaxDynamicSharedMemorySize, PWD_SMEM);
    cudaFuncSetAttribute(main_kernel, cudaFuncAttributeMaxDynamicSharedMemorySize, SMEM_MAIN);

    prep_kernel  <<<C_ + (T_*NSPIX*C_ + 255)/256, 256>>>(W);
    accum_kernel <<<(T_*H_*W_ + 7)/8, 256>>>(x, spix);
    pwd_kernel   <<<T_*49, 256, PWD_SMEM>>>();

    dim3 grid(W_/TW, H_/TH, T_);
    main_kernel<<<grid, 256, SMEM_MAIN>>>(x, spix, b_lin, w_scale, b_scale, out);
}

// round 13
// speedup vs baseline: 3.4631x; 1.3908x over previous
#include <cuda_runtime.h>
#include <cuda_fp16.h>
#include <cstdint>

#define T_ 2
#define C_ 64
#define H_ 160
#define W_ 160
#define KS 7
#define K2 49
#define NSPIX 196
#define FAN 3136

#define TH 8
#define TW 16
#define NPIX 128       // TH*TW
#define XR 14          // TH+6
#define XC 22          // TW+6
#define NS 308         // XR*XC
#define HROW 144       // 128B (64 fp16 channels) + 16 pad

// ---- dynamic smem layout (bytes) ----
#define OFF_HALO   0                   // 308*144 = 44352
#define OFF_B      44352               // 2 bufs * 8192 = 16384
#define OFF_RW     60736               // 128*49*4 = 25088
#define OFF_SCALE  85824               // 128*4 = 512
#define SMEM_MAIN  86336

#define PWD_STRIDE 67
#define PWD_SMEM   (NSPIX*PWD_STRIDE*4 + NSPIX*4)   // 53312

// ---- global scratch ----
__device__ float g_sums[T_*NSPIX*C_];
__device__ float g_cnts[T_*NSPIX];
__device__ float g_pwd[T_*NSPIX*NSPIX];
// per k: 8192B = 64 o-rows of 128B (64 fp16 c-values), XOR-swizzled 16B chunks
__device__ __align__(16) __half g_Wh[K2*C_*C_];

__device__ __forceinline__ int refl(int i, int n){
    if (i < 0) i = -i;
    if (i >= n) i = 2*n - 2 - i;
    return i;
}

__device__ __forceinline__ uint32_t smem_u32(const void* p){
    uint32_t a;
    asm("{ .reg .u64 t; cvta.to.shared.u64 t, %1; cvt.u32.u64 %0, t; }" : "=r"(a) : "l"(p));
    return a;
}

__device__ __forceinline__ void ldsm4(uint32_t* r, uint32_t addr){
    asm volatile("ldmatrix.sync.aligned.m8n8.x4.shared.b16 {%0,%1,%2,%3}, [%4];"
        : "=r"(r[0]), "=r"(r[1]), "=r"(r[2]), "=r"(r[3]) : "r"(addr));
}

__device__ __forceinline__ void mma16816(float* d, const uint32_t* a, const uint32_t* b){
    asm volatile("mma.sync.aligned.m16n8k16.row.col.f32.f16.f16.f32 "
        "{%0,%1,%2,%3}, {%4,%5,%6,%7}, {%8,%9}, {%0,%1,%2,%3};"
        : "+f"(d[0]), "+f"(d[1]), "+f"(d[2]), "+f"(d[3])
        : "r"(a[0]), "r"(a[1]), "r"(a[2]), "r"(a[3]), "r"(b[0]), "r"(b[1]));
}

__device__ __forceinline__ void hmul2(uint32_t& a, uint32_t s){
    asm("mul.rn.f16x2 %0, %0, %1;" : "+r"(a) : "r"(s));
}

__device__ __forceinline__ void cpa16(uint32_t dst, const void* src){
    asm volatile("cp.async.cg.shared.global [%0], [%1], 16;" :: "r"(dst), "l"(src) : "memory");
}
#define CP_COMMIT() asm volatile("cp.async.commit_group;" ::: "memory")
#define CP_WAIT(n)  asm volatile("cp.async.wait_group %0;" :: "n"(n) : "memory")

// ========================= prep kernels =========================

// blocks 0..63: convert W row o=blockIdx to swizzled fp16; rest: zero scratch
__global__ void prep_kernel(const float* __restrict__ W){
    int b = blockIdx.x;
    int tid = threadIdx.x;
    if (b < C_){
        __shared__ float wrow[FAN];
        int o = b;
        for (int i = tid; i < FAN; i += 256) wrow[i] = W[o*FAN + i];
        __syncthreads();
        uint32_t oxor = (uint32_t)((o & 7) << 4);
        char* base = (char*)g_Wh;
        for (int idx = tid; idx < FAN; idx += 256){
            int k = idx >> 6, c = idx & 63;
            __half hv = __float2half_rn(wrow[c*K2 + k]);
            uint32_t boff = (uint32_t)(k*8192 + o*128)
                          + ((((uint32_t)(c>>3))<<4) ^ oxor) + (uint32_t)((c&7)*2);
            *(unsigned short*)(base + boff) = __half_as_ushort(hv);
        }
    } else {
        int i = (b - C_)*256 + tid;
        if (i < T_*NSPIX*C_) g_sums[i] = 0.f;
        if (i < T_*NSPIX)    g_cnts[i] = 0.f;
    }
}

// one warp per pixel: lanes = channels -> coalesced RED
__global__ void accum_kernel(const float* __restrict__ x, const int* __restrict__ spix){
    int tid = threadIdx.x;
    int wi = tid >> 5, l = tid & 31;
    int pix = blockIdx.x*8 + wi;
    if (pix >= T_*H_*W_) return;
    int t = pix / (H_*W_);
    int hw = pix - t*(H_*W_);
    int s = spix[pix];
    const float* xp = x + (size_t)t*C_*H_*W_ + hw;
    float v0 = xp[(size_t)l*(H_*W_)];
    float v1 = xp[(size_t)(l+32)*(H_*W_)];
    float* dst = &g_sums[(t*NSPIX + s)*C_];
    atomicAdd(&dst[l],      v0);
    atomicAdd(&dst[l + 32], v1);
    if (l == 0) atomicAdd(&g_cnts[t*NSPIX + s], 1.0f);
}

// grid T_*49, 256 threads. Coalesced load, stride-67 pad, thread = s, 4 u per block.
__global__ void pwd_kernel(){
    extern __shared__ float sm[];
    float* down = sm;                       // [196][67]
    float* sq   = sm + NSPIX*PWD_STRIDE;
    int t  = blockIdx.x / 49;
    int ub = (blockIdx.x % 49) * 4;
    int tid = threadIdx.x;
    for (int i = tid; i < NSPIX*C_; i += 256){
        int s = i >> 6, c = i & 63;
        float cinv = 1.f / fmaxf(g_cnts[t*NSPIX + s], 1.f);
        down[s*PWD_STRIDE + c] = g_sums[i + t*NSPIX*C_] * cinv;
    }
    __syncthreads();
    if (tid < NSPIX){
        float q = 0.f;
        const float* a = &down[tid*PWD_STRIDE];
        #pragma unroll 8
        for (int c = 0; c < C_; c++) q += a[c]*a[c];
        sq[tid] = q;
    }
    __syncthreads();
    if (tid < NSPIX){
        const float* a = &down[tid*PWD_STRIDE];
        const float* u0 = &down[(ub+0)*PWD_STRIDE];
        const float* u1 = &down[(ub+1)*PWD_STRIDE];
        const float* u2 = &down[(ub+2)*PWD_STRIDE];
        const float* u3 = &down[(ub+3)*PWD_STRIDE];
        float d0=0.f, d1=0.f, d2=0.f, d3=0.f;
        #pragma unroll 8
        for (int c = 0; c < C_; c++){
            float av = a[c];
            d0 += av*u0[c]; d1 += av*u1[c]; d2 += av*u2[c]; d3 += av*u3[c];
        }
        float qs = sq[tid];
        float* dst = &g_pwd[(size_t)(t*NSPIX + tid)*NSPIX + ub];
        dst[0] = fmaxf(qs + sq[ub+0] - 2.f*d0, 0.f);
        dst[1] = fmaxf(qs + sq[ub+1] - 2.f*d1, 0.f);
        dst[2] = fmaxf(qs + sq[ub+2] - 2.f*d2, 0.f);
        dst[3] = fmaxf(qs + sq[ub+3] - 2.f*d3, 0.f);
    }
}

// ========================= main kernel =========================
// 400 CTAs (8x16 px), 256 threads (8 warps: 4m x 2n, warp tile m32 x n32), occ 2.
// 1-pass fp16, rw folded into A fragments (f16x2 mul), fp32 MMA accumulate.

__global__ void __launch_bounds__(256, 2) main_kernel(
    const float* __restrict__ x, const int* __restrict__ spix,
    const float* __restrict__ b_lin, const float* __restrict__ w_scale,
    const float* __restrict__ b_scale, float* __restrict__ out)
{
    extern __shared__ char smem[];
    uint32_t sb = smem_u32(smem);
    int tid = threadIdx.x;
    int wi = tid >> 5, l = tid & 31;
    int mi = wi >> 1, ni = wi & 1;
    int t = blockIdx.z;
    int gh0 = blockIdx.y*TH, gw0 = blockIdx.x*TW;

    float* scale_s = (float*)(smem + OFF_SCALE);
    float* rw      = (float*)(smem + OFF_RW);

    // ---- phase 1: per-pixel scale ----
    if (tid < NPIX){
        int gh = gh0 + (tid >> 4), gw = gw0 + (tid & 15);
        const float* xp = x + (size_t)t*C_*H_*W_ + gh*W_ + gw;
        float nsq = 0.f, dot = 0.f;
        #pragma unroll 8
        for (int c = 0; c < C_; c++){
            float v = xp[(size_t)c*H_*W_];
            nsq += v*v;
            dot += w_scale[c]*v;
        }
        float z  = dot / (sqrtf(nsq) + 1e-10f) + b_scale[0];
        float sp = fmaxf(z, 0.f) + log1pf(expf(-fabsf(z)));
        scale_s[tid] = 10.f * sp;
    }

    // ---- phase 2: halo load + fp16 convert: row s = [64 fp16][pad16] ----
    for (int i = tid; i < NS*32; i += 256){
        int s  = i >> 5;
        int cp = i & 31;          // channel pair
        int rr = s / XC, cc2 = s - rr*XC;
        int gh = refl(gh0 + rr - 3, H_), gw = refl(gw0 + cc2 - 3, W_);
        const float* xp = x + ((size_t)(t*C_ + 2*cp)*H_ + gh)*W_ + gw;
        float v0 = xp[0], v1 = xp[(size_t)H_*W_];
        __half h0 = __float2half_rn(v0), h1 = __float2half_rn(v1);
        uint32_t uh = (uint32_t)__half_as_ushort(h0) | ((uint32_t)__half_as_ushort(h1) << 16);
        *(uint32_t*)(smem + OFF_HALO + s*HROW + cp*4) = uh;
    }
    __syncthreads();

    // ---- phase 3: rw ----
    for (int item = tid; item < NPIX*K2; item += 256){
        int p  = item / K2, k = item - p*K2;
        int ki = k / KS,  kj = k - ki*KS;
        int gh = gh0 + (p >> 4), gw = gw0 + (p & 15);
        int rh = refl(gh + ki - 3, H_), rc = refl(gw + kj - 3, W_);
        int sc = spix[(t*H_ + gh)*W_ + gw];
        int nb = spix[(t*H_ + rh)*W_ + rc];
        rw[item] = expf(-scale_s[p] * g_pwd[(size_t)(t*NSPIX + sc)*NSPIX + nb]);
    }
    __syncthreads();
    if (tid < NPIX){
        float m = 0.f;
        #pragma unroll
        for (int k = 0; k < K2; k++) m = fmaxf(m, rw[tid*K2 + k]);
        float inv = 1.f / (1e-5f + m);
        #pragma unroll
        for (int k = 0; k < K2; k++) rw[tid*K2 + k] *= inv;
    }

    // ---- per-lane static addressing ----
    // A m16 tile tb = one image row of 16 px; warp mi owns tiles 2mi, 2mi+1.
    int rowA = (l & 7) | (((l >> 3) & 1) << 3);   // w within tile
    int colh = (l >> 4) & 1;
    int tb0 = mi*2, tb1 = mi*2 + 1;
    uint32_t aStat0 = sb + OFF_HALO + (uint32_t)((tb0*XC + rowA)*HROW) + colh*16;
    uint32_t aStat1 = sb + OFF_HALO + (uint32_t)((tb1*XC + rowA)*HROW) + colh*16;

    int oRow  = (l & 7) | (((l >> 4) & 1) << 3);
    uint32_t bhalf16 = (uint32_t)(((l >> 3) & 1) << 4);
    int o0 = ni*32 + oRow;
    int o1 = o0 + 16;
    uint32_t bOff0 = (uint32_t)(o0*128), bXor0 = (uint32_t)((o0 & 7) << 4);
    uint32_t bOff1 = (uint32_t)(o1*128), bXor1 = (uint32_t)((o1 & 7) << 4);

    // rw rows for my accumulators
    int w_lo = l >> 2;                 // d0,d1 row (w pos in tile)
    int p00 = (tb0*16 + w_lo)*K2;      // tile0 lo
    int p01 = p00 + 8*K2;              // tile0 hi
    int p10 = (tb1*16 + w_lo)*K2;
    int p11 = p10 + 8*K2;

    // ---- preload B for k=0 (8KB: 512 x 16B, 2 per thread) ----
    {
        const char* src = (const char*)g_Wh;
        uint32_t dst = sb + OFF_B;
        cpa16(dst + tid*16,       src + tid*16);
        cpa16(dst + (tid+256)*16, src + (tid+256)*16);
        CP_COMMIT();
    }

    float acc0[16], acc1[16];
    #pragma unroll
    for (int i = 0; i < 16; i++){ acc0[i] = 0.f; acc1[i] = 0.f; }

    // ---- main loop over 49 kernel offsets ----
    for (int k = 0; k < K2; k++){
        int cur = k & 1;
        if (k + 1 < K2){
            const char* src = (const char*)g_Wh + (size_t)(k+1)*8192;
            uint32_t dst = sb + OFF_B + (cur^1)*8192;
            cpa16(dst + tid*16,       src + tid*16);
            cpa16(dst + (tid+256)*16, src + (tid+256)*16);
            CP_COMMIT();
            CP_WAIT(1);
        } else {
            CP_WAIT(0);
        }
        __syncthreads();

        uint32_t bBase = sb + OFF_B + cur*8192;
        int ki = k / KS, kj = k - ki*KS;
        uint32_t koff = (uint32_t)((ki*XC + kj)*HROW);
        uint32_t aA0 = aStat0 + koff;
        uint32_t aA1 = aStat1 + koff;

        // rw scales for this k as f16x2 (same value in both halves)
        uint32_t s00, s01, s10, s11;
        {
            __half2 h;
            h = __floats2half2_rn(rw[p00 + k], rw[p00 + k]); s00 = *(uint32_t*)&h;
            h = __floats2half2_rn(rw[p01 + k], rw[p01 + k]); s01 = *(uint32_t*)&h;
            h = __floats2half2_rn(rw[p10 + k], rw[p10 + k]); s10 = *(uint32_t*)&h;
            h = __floats2half2_rn(rw[p11 + k], rw[p11 + k]); s11 = *(uint32_t*)&h;
        }

        #pragma unroll
        for (int kc = 0; kc < 4; kc++){
            uint32_t a0[4], a1[4];
            ldsm4(a0, aA0 + kc*32);
            ldsm4(a1, aA1 + kc*32);
            // fold rw into A: regs 0,2 = row l/4 (lo); regs 1,3 = row l/4+8 (hi)
            hmul2(a0[0], s00); hmul2(a0[2], s00);
            hmul2(a0[1], s01); hmul2(a0[3], s01);
            hmul2(a1[0], s10); hmul2(a1[2], s10);
            hmul2(a1[1], s11); hmul2(a1[3], s11);

            uint32_t csw = (uint32_t)(kc*32) + bhalf16;
            uint32_t b0[4], b1[4];
            ldsm4(b0, bBase + bOff0 + (csw ^ bXor0));
            ldsm4(b1, bBase + bOff1 + (csw ^ bXor1));

            mma16816(&acc0[0],  a0, b0);
            mma16816(&acc0[4],  a0, b0+2);
            mma16816(&acc0[8],  a0, b1);
            mma16816(&acc0[12], a0, b1+2);
            mma16816(&acc1[0],  a1, b0);
            mma16816(&acc1[4],  a1, b0+2);
            mma16816(&acc1[8],  a1, b1);
            mma16816(&acc1[12], a1, b1+2);
        }
        __syncthreads();   // all warps done with B buf before overwrite
    }

    // ---- store ----
    #pragma unroll
    for (int tt = 0; tt < 2; tt++){
        float* a = tt ? acc1 : acc0;
        int gh = gh0 + mi*2 + tt;
        int gwl = gw0 + w_lo;
        int gwh = gwl + 8;
        #pragma unroll
        for (int g = 0; g < 4; g++){
            int o = ni*32 + g*8 + 2*(l & 3);
            float b0 = b_lin[o], b1 = b_lin[o+1];
            out[((size_t)(t*C_ + o  )*H_ + gh)*W_ + gwl] = a[g*4 + 0] + b0;
            out[((size_t)(t*C_ + o+1)*H_ + gh)*W_ + gwl] = a[g*4 + 1] + b1;
            out[((size_t)(t*C_ + o  )*H_ + gh)*W_ + gwh] = a[g*4 + 2] + b0;
            out[((size_t)(t*C_ + o+1)*H_ + gh)*W_ + gwh] = a[g*4 + 3] + b1;
        }
    }
}

// ========================= launch =========================

extern "C" void kernel_launch(void* const* d_in, const int* in_sizes, int n_in,
                              void* d_out, int out_size)
{
    const float* x       = (const float*)d_in[0];
    const int*   spix    = (const int*)  d_in[1];
    const float* W       = (const float*)d_in[2];
    const float* b_lin   = (const float*)d_in[3];
    const float* w_scale = (const float*)d_in[4];
    const float* b_scale = (const float*)d_in[5];
    float* out = (float*)d_out;

    cudaFuncSetAttribute(pwd_kernel,  cudaFuncAttributeMaxDynamicSharedMemorySize, PWD_SMEM);
    cudaFuncSetAttribute(main_kernel, cudaFuncAttributeMaxDynamicSharedMemorySize, SMEM_MAIN);

    prep_kernel  <<<C_ + (T_*NSPIX*C_ + 255)/256, 256>>>(W);
    accum_kernel <<<(T_*H_*W_ + 7)/8, 256>>>(x, spix);
    pwd_kernel   <<<T_*49, 256, PWD_SMEM>>>();

    dim3 grid(W_/TW, H_/TH, T_);
    main_kernel<<<grid, 256, SMEM_MAIN>>>(x, spix, b_lin, w_scale, b_scale, out);
}